// round 15
// baseline (speedup 1.0000x reference)
#include <cuda_runtime.h>

// Phase-split warp-specialized pipeline, 384 threads/CTA, 2 CTAs/SM.
// TT=16 tiles, TRIPLE-buffered; slot loop UNROLLED x3 so all buffer selectors
// are compile-time literals (no %3, pointers hoisted). Per slot k:
//   warps 0-3:  P3(k-1) reads buf[(k-1)%3]
//   warps 4-7:  P1(k+1) writes buf[(k+1)%3] from x[(k+1)%3]
//   warps 8-10: P2(k) in place on buf[k%3]
//   warp 11:    stages x tile (k+2) into x[(k+2)%3]

typedef unsigned long long u64;

#define NTHREADS 384
#define TT 16
#define NTILES 64
#define TPAD 20
#define XPAD 20
#define WPAD 20
#define XSZ  (16 * XPAD)
#define BSZ  (256 * TPAD)

__device__ __forceinline__ u64 ffma2(u64 a, u64 b, u64 c) {
    u64 d; asm("fma.rn.f32x2 %0, %1, %2, %3;" : "=l"(d) : "l"(a), "l"(b), "l"(c)); return d;
}
__device__ __forceinline__ u64 addf2(u64 a, u64 b) {
    u64 d; asm("add.rn.f32x2 %0, %1, %2;" : "=l"(d) : "l"(a), "l"(b)); return d;
}
__device__ __forceinline__ u64 pack2(float a, float b) {
    u64 r; asm("mov.b64 %0, {%1, %2};" : "=l"(r) : "f"(a), "f"(b)); return r;
}
__device__ __forceinline__ u64 dup2(float a) {
    u64 r; asm("mov.b64 %0, {%1, %1};" : "=l"(r) : "f"(a)); return r;
}
__device__ __forceinline__ float2 unpack2(u64 v) {
    float2 r; asm("mov.b64 {%0, %1}, %2;" : "=f"(r.x), "=f"(r.y) : "l"(v)); return r;
}

// ---- material constants (reference float32 values) ----
#define NUv    0.3f
#define CEL00  (200.0f / 0.91f)
#define CEL01  (CEL00 * 0.3f)
#define CEL22  (CEL00 * 0.35f)
#define INV_E  (1.0f / 200.0f)
#define INV_G  (2.6f / 200.0f)
#define GMODc  (200.0f / 2.6f)
#define SY0c   2.0f
#define HARDc  10.0f
#define INV3GH (1.0f / (3.0f * GMODc + HARDc))
#define KPEN   50.0f
#define D0c    0.1f
#define INV_DFm (1.0f / 0.9f)

__device__ __forceinline__ void j2_step(float& e1, float& e2, float& e12,
                                        float& ep1, float& ep2, float& ep12, float& epbar)
{
    float d1 = e1 - ep1, d2 = e2 - ep2, d12 = e12 - ep12;
    float s1  = CEL00 * d1 + CEL01 * d2;
    float s2  = CEL01 * d1 + CEL00 * d2;
    float s12 = CEL22 * d12;
    float qv  = fmaxf(s1 * s1 - s1 * s2 + s2 * s2 + 3.0f * s12 * s12, 1e-12f);
    float rs  = rsqrtf(qv);
    float seq = qv * rs;
    float fy  = seq - (SY0c + HARDc * epbar);
    bool  pl  = fy > 0.0f;
    epbar += fmaxf(fy, 0.0f) * INV3GH;
    float r = pl ? (SY0c + HARDc * epbar) * rs : 1.0f;
    s1 *= r; s2 *= r; s12 *= r;
    ep1  = pl ? e1  - (s1 - NUv * s2) * INV_E : ep1;
    ep2  = pl ? e2  - (s2 - NUv * s1) * INV_E : ep2;
    ep12 = pl ? e12 - s12 * INV_G             : ep12;
    e1 = s1; e2 = s2; e12 = s12;
}

__device__ __forceinline__ void coh_step(float& dn, float& ds, float& hist)
{
    float dnp = fmaxf(dn, 0.0f);
    float q2  = fmaxf(dnp * dnp + ds * ds, 1e-12f);
    float lam = q2 * rsqrtf(q2);
    hist = fmaxf(hist, lam);
    float dmg = __fdividef(hist - D0c, hist) * INV_DFm;
    dmg = fminf(fmaxf(dmg, 0.0f), 1.0f);
    float omd = 1.0f - dmg;
    float tn = KPEN * dn * (dn > 0.0f ? omd : 1.0f);
    ds = omd * KPEN * ds;
    dn = tn;
}

// channel -> buf row (cohesive channels stored comp-planar)
__device__ __forceinline__ int row_of(int c) {
    return (c < 192) ? c : 192 + ((c - 192) >> 1) + 32 * (c & 1);
}

__global__ void __launch_bounds__(NTHREADS, 2)
fused_fea_kernel(const float* __restrict__ x, const float* __restrict__ W1,
                 const float* __restrict__ W2, float* __restrict__ out)
{
    extern __shared__ float sm[];
    float* SW2s = sm;                    // 256*WPAD, softplus(W2) [l][o]
    float* xsd  = sm + 256 * WPAD;       // 3 * XSZ, x transposed [f][t]
    float* buf  = xsd + 3 * XSZ;         // 3 * BSZ, [l][t]

    const int tid = threadIdx.x;
    const int b   = blockIdx.x;

    const float* xb = x   + (size_t)b * (1024 * 16);
    float*       ob = out + (size_t)b * (1024 * 16);

    // ---- Prologue: softplus(W2); stager fills x tiles 0 and 1 ----
    for (int i = tid; i < 4096; i += NTHREADS) {
        int o = i >> 8, l = i & 255;
        SW2s[l * WPAD + o] = log1pf(expf(W2[i]));
    }
    const int sj  = tid - 352;           // stager index
    const int sjt = sj >> 1, sjh = sj & 1;
    if (tid >= 352) {
#pragma unroll
        for (int tile = 0; tile < 2; ++tile) {
            const float4* src = (const float4*)(xb + (tile * TT + sjt) * 16 + sjh * 8);
            float4 v0 = src[0], v1 = src[1];
            float* dst = xsd + tile * XSZ + sjh * 8 * XPAD + sjt;
            dst[0*XPAD] = v0.x; dst[1*XPAD] = v0.y; dst[2*XPAD] = v0.z; dst[3*XPAD] = v0.w;
            dst[4*XPAD] = v1.x; dst[5*XPAD] = v1.y; dst[6*XPAD] = v1.z; dst[7*XPAD] = v1.w;
        }
    }

    const bool isP3 = (tid < 128);
    const bool isP1 = (tid >= 128 && tid < 256);

    // P1 warps: packed channel pair (c, c+128), c = tid-128; hoisted dst ptrs.
    u64 wreg[16];
    float* p1r0 = buf;  float* p1r1 = buf;
    if (isP1) {
        const int c = tid - 128;
        p1r0 = buf + row_of(c) * TPAD;
        p1r1 = buf + row_of(c + 128) * TPAD;
#pragma unroll
        for (int f = 0; f < 16; ++f)
            wreg[f] = pack2(W1[c * 16 + f], W1[(c + 128) * 16 + f]);
    }

    // S chain state + hoisted row bases.
    float ep1 = 0.f, ep2 = 0.f, ep12 = 0.f, epbar = 0.f, hist = 0.f;
    const int s = tid - 256;
    float* sb_bulk = buf + ((s >= 0 && s < 64) ? (3 * s) * TPAD : 0);
    float* sb_dn   = buf + ((s >= 64 && s < 96) ? (192 + (s - 64)) * TPAD : 0);
    float* sb_ds   = buf + ((s >= 64 && s < 96) ? (224 + (s - 64)) * TPAD : 0);

    // P3 coords + hoisted bases: lc = l-strip, oq = output quad, tb = t-quad.
    const int lc = tid & 7;
    const int oq = (tid >> 3) & 3;
    const int tb = tid >> 5;             // 0..3 for P3 warps
    const float* p3_yb = buf + lc * TPAD + 4 * tb;
    const float* p3_yc = buf + (192 + (lc >> 1) + 32 * (lc & 1)) * TPAD + 4 * tb;
    const float* p3_w  = SW2s + lc * WPAD + 4 * oq;

    __syncthreads();

    // ===== P1: channel pair o-packed, 16 t (4 groups of 4) =====
#define P1_TILE(BSEL, XSEL)                                                   \
    {                                                                         \
        const float* xsb = xsd + (XSEL) * XSZ;                                \
        _Pragma("unroll")                                                     \
        for (int g = 0; g < 4; ++g) {                                         \
            const int t = g * 4;                                              \
            u64 a0 = 0, a1 = 0, a2 = 0, a3 = 0;                               \
            _Pragma("unroll")                                                 \
            for (int f = 0; f < 16; ++f) {                                    \
                float4 xq = *(const float4*)(xsb + f * XPAD + t);             \
                a0 = ffma2(wreg[f], dup2(xq.x), a0);                          \
                a1 = ffma2(wreg[f], dup2(xq.y), a1);                          \
                a2 = ffma2(wreg[f], dup2(xq.z), a2);                          \
                a3 = ffma2(wreg[f], dup2(xq.w), a3);                          \
            }                                                                 \
            float2 h0 = unpack2(a0), h1 = unpack2(a1);                        \
            float2 h2 = unpack2(a2), h3 = unpack2(a3);                        \
            float4 v0; v0.x = h0.x; v0.y = h1.x; v0.z = h2.x; v0.w = h3.x;    \
            float4 v1; v1.x = h0.y; v1.y = h1.y; v1.z = h2.y; v1.w = h3.y;    \
            *(float4*)(p1r0 + (BSEL) * BSZ + t) = v0;                         \
            *(float4*)(p1r1 + (BSEL) * BSZ + t) = v1;                         \
        }                                                                     \
    }

    // ===== P3: warp = t-quad tb; thread (lc, oq); R10 inner loop =====
#define P3_TILE(BSEL, TOUT)                                                   \
    {                                                                         \
        u64 acc[8];                                                           \
        _Pragma("unroll")                                                     \
        for (int m = 0; m < 8; ++m) acc[m] = 0ull;                            \
        const float* ybulk = p3_yb + (BSEL) * BSZ;                            \
        _Pragma("unroll 4")                                                   \
        for (int i = 0; i < 24; ++i) {                                        \
            ulonglong2 yv = *(const ulonglong2*)(ybulk + i * 8 * TPAD);       \
            ulonglong2 wv = *(const ulonglong2*)(p3_w + i * 8 * WPAD);        \
            float2 y01 = unpack2(yv.x), y23 = unpack2(yv.y);                  \
            u64 y0 = dup2(y01.x), y1 = dup2(y01.y);                           \
            u64 y2 = dup2(y23.x), y3 = dup2(y23.y);                           \
            acc[0] = ffma2(wv.x, y0, acc[0]); acc[1] = ffma2(wv.y, y0, acc[1]); \
            acc[2] = ffma2(wv.x, y1, acc[2]); acc[3] = ffma2(wv.y, y1, acc[3]); \
            acc[4] = ffma2(wv.x, y2, acc[4]); acc[5] = ffma2(wv.y, y2, acc[5]); \
            acc[6] = ffma2(wv.x, y3, acc[6]); acc[7] = ffma2(wv.y, y3, acc[7]); \
        }                                                                     \
        const float* ycoh = p3_yc + (BSEL) * BSZ;                             \
        _Pragma("unroll 4")                                                   \
        for (int i = 24; i < 32; ++i) {                                       \
            ulonglong2 yv = *(const ulonglong2*)(ycoh + (i - 24) * 4 * TPAD); \
            ulonglong2 wv = *(const ulonglong2*)(p3_w + i * 8 * WPAD);        \
            float2 y01 = unpack2(yv.x), y23 = unpack2(yv.y);                  \
            u64 y0 = dup2(y01.x), y1 = dup2(y01.y);                           \
            u64 y2 = dup2(y23.x), y3 = dup2(y23.y);                           \
            acc[0] = ffma2(wv.x, y0, acc[0]); acc[1] = ffma2(wv.y, y0, acc[1]); \
            acc[2] = ffma2(wv.x, y1, acc[2]); acc[3] = ffma2(wv.y, y1, acc[3]); \
            acc[4] = ffma2(wv.x, y2, acc[4]); acc[5] = ffma2(wv.y, y2, acc[5]); \
            acc[6] = ffma2(wv.x, y3, acc[6]); acc[7] = ffma2(wv.y, y3, acc[7]); \
        }                                                                     \
        _Pragma("unroll")                                                     \
        for (int m = 0; m < 8; ++m) {                                         \
            acc[m] = addf2(acc[m], __shfl_xor_sync(0xffffffffu, acc[m], 1));  \
            acc[m] = addf2(acc[m], __shfl_xor_sync(0xffffffffu, acc[m], 2));  \
            acc[m] = addf2(acc[m], __shfl_xor_sync(0xffffffffu, acc[m], 4));  \
        }                                                                     \
        if (lc == 0) {                                                        \
            float* ogp = ob + (size_t)((TOUT) + 4 * tb) * 16 + 4 * oq;        \
            _Pragma("unroll")                                                 \
            for (int j = 0; j < 4; ++j) {                                     \
                float2 p0 = unpack2(acc[2 * j]);                              \
                float2 p1 = unpack2(acc[2 * j + 1]);                          \
                float4 v; v.x = p0.x; v.y = p0.y; v.z = p1.x; v.w = p1.y;     \
                *(float4*)(ogp + j * 16) = v;                                 \
            }                                                                 \
        }                                                                     \
    }

    // ===== One slot with literal buffer selectors and range guards =====
#define SLOT(K, BM1, B0, BP1, BP2)                                            \
    {                                                                         \
        const int k = (K);                                                    \
        if (isP3) {                                                           \
            if (k >= 1 && k <= NTILES) P3_TILE(BM1, (k - 1) * TT);            \
        } else if (isP1) {                                                    \
            if (k + 1 < NTILES) P1_TILE(BP1, BP1);                            \
        } else if (s < 64) {                                                  \
            if (k < NTILES) {                                                 \
                float* r0 = sb_bulk + (B0) * BSZ;                             \
                _Pragma("unroll")                                             \
                for (int g = 0; g < 4; ++g) {                                 \
                    float4 E1 = *(float4*)(r0 + 4 * g);                       \
                    float4 E2 = *(float4*)(r0 + TPAD + 4 * g);                \
                    float4 E3 = *(float4*)(r0 + 2 * TPAD + 4 * g);            \
                    j2_step(E1.x, E2.x, E3.x, ep1, ep2, ep12, epbar);         \
                    j2_step(E1.y, E2.y, E3.y, ep1, ep2, ep12, epbar);         \
                    j2_step(E1.z, E2.z, E3.z, ep1, ep2, ep12, epbar);         \
                    j2_step(E1.w, E2.w, E3.w, ep1, ep2, ep12, epbar);         \
                    *(float4*)(r0 + 4 * g) = E1;                              \
                    *(float4*)(r0 + TPAD + 4 * g) = E2;                       \
                    *(float4*)(r0 + 2 * TPAD + 4 * g) = E3;                   \
                }                                                             \
            }                                                                 \
        } else if (s < 96) {                                                  \
            if (k < NTILES) {                                                 \
                float* rdn = sb_dn + (B0) * BSZ;                              \
                float* rds = sb_ds + (B0) * BSZ;                              \
                _Pragma("unroll")                                             \
                for (int g = 0; g < 4; ++g) {                                 \
                    float4 DN = *(float4*)(rdn + 4 * g);                      \
                    float4 DS = *(float4*)(rds + 4 * g);                      \
                    coh_step(DN.x, DS.x, hist);                               \
                    coh_step(DN.y, DS.y, hist);                               \
                    coh_step(DN.z, DS.z, hist);                               \
                    coh_step(DN.w, DS.w, hist);                               \
                    *(float4*)(rdn + 4 * g) = DN;                             \
                    *(float4*)(rds + 4 * g) = DS;                             \
                }                                                             \
            }                                                                 \
        } else {                                                              \
            if (k + 2 < NTILES) {                                             \
                const float4* src =                                           \
                    (const float4*)(xb + ((k + 2) * TT + sjt) * 16 + sjh * 8);\
                float4 v0 = src[0], v1 = src[1];                              \
                float* dst = xsd + (BP2) * XSZ + sjh * 8 * XPAD + sjt;        \
                dst[0*XPAD] = v0.x; dst[1*XPAD] = v0.y;                       \
                dst[2*XPAD] = v0.z; dst[3*XPAD] = v0.w;                       \
                dst[4*XPAD] = v1.x; dst[5*XPAD] = v1.y;                       \
                dst[6*XPAD] = v1.z; dst[7*XPAD] = v1.w;                       \
            }                                                                 \
        }                                                                     \
        __syncthreads();                                                      \
    }

    // ---- Fill: P1(0) into buf[0] ----
    if (isP1) P1_TILE(0, 0);
    __syncthreads();

    // ---- Pipelined slots, unrolled x3 (66 slots; slot 65 is a no-op) ----
    for (int kk = 0; kk < 66; kk += 3) {
        SLOT(kk,     2, 0, 1, 2);
        SLOT(kk + 1, 0, 1, 2, 0);
        SLOT(kk + 2, 1, 2, 0, 1);
    }
}

extern "C" void kernel_launch(void* const* d_in, const int* in_sizes, int n_in,
                              void* d_out, int out_size)
{
    const float* x  = (const float*)d_in[0];
    const float* W1 = (const float*)d_in[1];
    const float* W2 = (const float*)d_in[2];
    float* out = (float*)d_out;

    const size_t smem = (size_t)(256 * WPAD + 3 * XSZ + 3 * BSZ) * sizeof(float); // 85760 B
    cudaFuncSetAttribute(fused_fea_kernel, cudaFuncAttributeMaxDynamicSharedMemorySize, (int)smem);
    fused_fea_kernel<<<256, NTHREADS, smem>>>(x, W1, W2, out);
}

// round 16
// speedup vs baseline: 1.0271x; 1.0271x over previous
#include <cuda_runtime.h>

// Phase-split warp-specialized pipeline, 384 threads/CTA, 2 CTAs/SM.
// TT=16 tiles, TRIPLE-buffered, ROLLED slot loop (I$-small) with rotating
// register pointers (no %3, no per-slot base recompute). Per slot k:
//   warps 0-3:  P3(k-1) reads buf[(k-1)%3]
//   warps 4-7:  P1(k+1) writes buf[(k+1)%3] from x[(k+1)%3]
//   warps 8-10: P2(k) in place on buf[k%3]
//   warp 11:    stages x tile (k+2) into x[(k+2)%3]

typedef unsigned long long u64;

#define NTHREADS 384
#define TT 16
#define NTILES 64
#define TPAD 20
#define XPAD 20
#define WPAD 20
#define XSZ  (16 * XPAD)
#define BSZ  (256 * TPAD)

__device__ __forceinline__ u64 ffma2(u64 a, u64 b, u64 c) {
    u64 d; asm("fma.rn.f32x2 %0, %1, %2, %3;" : "=l"(d) : "l"(a), "l"(b), "l"(c)); return d;
}
__device__ __forceinline__ u64 addf2(u64 a, u64 b) {
    u64 d; asm("add.rn.f32x2 %0, %1, %2;" : "=l"(d) : "l"(a), "l"(b)); return d;
}
__device__ __forceinline__ u64 pack2(float a, float b) {
    u64 r; asm("mov.b64 %0, {%1, %2};" : "=l"(r) : "f"(a), "f"(b)); return r;
}
__device__ __forceinline__ u64 dup2(float a) {
    u64 r; asm("mov.b64 %0, {%1, %1};" : "=l"(r) : "f"(a)); return r;
}
__device__ __forceinline__ float2 unpack2(u64 v) {
    float2 r; asm("mov.b64 {%0, %1}, %2;" : "=f"(r.x), "=f"(r.y) : "l"(v)); return r;
}

// ---- material constants (reference float32 values) ----
#define NUv    0.3f
#define CEL00  (200.0f / 0.91f)
#define CEL01  (CEL00 * 0.3f)
#define CEL22  (CEL00 * 0.35f)
#define INV_E  (1.0f / 200.0f)
#define INV_G  (2.6f / 200.0f)
#define GMODc  (200.0f / 2.6f)
#define SY0c   2.0f
#define HARDc  10.0f
#define INV3GH (1.0f / (3.0f * GMODc + HARDc))
#define KPEN   50.0f
#define D0c    0.1f
#define INV_DFm (1.0f / 0.9f)

__device__ __forceinline__ void j2_step(float& e1, float& e2, float& e12,
                                        float& ep1, float& ep2, float& ep12, float& epbar)
{
    float d1 = e1 - ep1, d2 = e2 - ep2, d12 = e12 - ep12;
    float s1  = CEL00 * d1 + CEL01 * d2;
    float s2  = CEL01 * d1 + CEL00 * d2;
    float s12 = CEL22 * d12;
    float qv  = fmaxf(s1 * s1 - s1 * s2 + s2 * s2 + 3.0f * s12 * s12, 1e-12f);
    float rs  = rsqrtf(qv);
    float seq = qv * rs;
    float fy  = seq - (SY0c + HARDc * epbar);
    bool  pl  = fy > 0.0f;
    epbar += fmaxf(fy, 0.0f) * INV3GH;
    float r = pl ? (SY0c + HARDc * epbar) * rs : 1.0f;
    s1 *= r; s2 *= r; s12 *= r;
    ep1  = pl ? e1  - (s1 - NUv * s2) * INV_E : ep1;
    ep2  = pl ? e2  - (s2 - NUv * s1) * INV_E : ep2;
    ep12 = pl ? e12 - s12 * INV_G             : ep12;
    e1 = s1; e2 = s2; e12 = s12;
}

__device__ __forceinline__ void coh_step(float& dn, float& ds, float& hist)
{
    float dnp = fmaxf(dn, 0.0f);
    float q2  = fmaxf(dnp * dnp + ds * ds, 1e-12f);
    float lam = q2 * rsqrtf(q2);
    hist = fmaxf(hist, lam);
    float dmg = __fdividef(hist - D0c, hist) * INV_DFm;
    dmg = fminf(fmaxf(dmg, 0.0f), 1.0f);
    float omd = 1.0f - dmg;
    float tn = KPEN * dn * (dn > 0.0f ? omd : 1.0f);
    ds = omd * KPEN * ds;
    dn = tn;
}

// channel -> buf row (cohesive channels stored comp-planar)
__device__ __forceinline__ int row_of(int c) {
    return (c < 192) ? c : 192 + ((c - 192) >> 1) + 32 * (c & 1);
}

__global__ void __launch_bounds__(NTHREADS, 2)
fused_fea_kernel(const float* __restrict__ x, const float* __restrict__ W1,
                 const float* __restrict__ W2, float* __restrict__ out)
{
    extern __shared__ float sm[];
    float* SW2s = sm;                    // 256*WPAD, softplus(W2) [l][o]
    float* xsd  = sm + 256 * WPAD;       // 3 * XSZ, x transposed [f][t]
    float* buf  = xsd + 3 * XSZ;         // 3 * BSZ, [l][t]

    const int tid = threadIdx.x;
    const int b   = blockIdx.x;

    const float* xb = x   + (size_t)b * (1024 * 16);
    float*       ob = out + (size_t)b * (1024 * 16);

    // ---- Prologue: softplus(W2); stager fills x tiles 0 and 1 ----
    for (int i = tid; i < 4096; i += NTHREADS) {
        int o = i >> 8, l = i & 255;
        SW2s[l * WPAD + o] = log1pf(expf(W2[i]));
    }
    const int sj  = tid - 352;
    const int sjt = sj >> 1, sjh = sj & 1;
    if (tid >= 352) {
#pragma unroll
        for (int tile = 0; tile < 2; ++tile) {
            const float4* src = (const float4*)(xb + (tile * TT + sjt) * 16 + sjh * 8);
            float4 v0 = src[0], v1 = src[1];
            float* dst = xsd + tile * XSZ + sjh * 8 * XPAD + sjt;
            dst[0*XPAD] = v0.x; dst[1*XPAD] = v0.y; dst[2*XPAD] = v0.z; dst[3*XPAD] = v0.w;
            dst[4*XPAD] = v1.x; dst[5*XPAD] = v1.y; dst[6*XPAD] = v1.z; dst[7*XPAD] = v1.w;
        }
    }

    const bool isP3 = (tid < 128);
    const bool isP1 = (tid >= 128 && tid < 256);
    const int  s    = tid - 256;

    // ---- Role state: rotating register pointers (advance at slot start) ----
    // P1: writes buffer (k+1)%3. Init at buffer 0; advance -> buffer 1 at k=0.
    u64 wreg[16];
    float* p1r0 = buf;  float* p1r1 = buf;          // rotating
    float* p1r0_base = buf;  float* p1r1_base = buf; // buffer-0 ptrs (fill + wrap)
    const float* p1xs = xsd;                         // rotating x ptr
    if (isP1) {
        const int c = tid - 128;
        p1r0_base = buf + row_of(c) * TPAD;
        p1r1_base = buf + row_of(c + 128) * TPAD;
        p1r0 = p1r0_base;
        p1r1 = p1r1_base;
#pragma unroll
        for (int f = 0; f < 16; ++f)
            wreg[f] = pack2(W1[c * 16 + f], W1[(c + 128) * 16 + f]);
    }

    // S: uses buffer k%3. Init at buffer 2; advance -> buffer 0 at k=0.
    float ep1 = 0.f, ep2 = 0.f, ep12 = 0.f, epbar = 0.f, hist = 0.f;
    float* sb_a = buf;  float* sb_b = buf;          // rotating (bulk: rows 3s,3s+1,3s+2 via sb_a; coh: dn=sb_a, ds=sb_b)
    float* sb_a_base = buf;  float* sb_b_base = buf;
    if (s >= 0 && s < 64) {
        sb_a_base = buf + (3 * s) * TPAD;
        sb_b_base = sb_a_base;                       // unused second ptr
    } else if (s >= 64 && s < 96) {
        sb_a_base = buf + (192 + (s - 64)) * TPAD;
        sb_b_base = buf + (224 + (s - 64)) * TPAD;
    }
    sb_a = sb_a_base + 2 * BSZ;
    sb_b = sb_b_base + 2 * BSZ;

    // P3: reads buffer (k-1)%3. Init at buffer 1; advance -> buffer 2 at k=0
    // (unused), buffer 0 at k=1 (correct).
    const int lc = tid & 7;
    const int oq = (tid >> 3) & 3;
    const int tb = tid >> 5;
    const float* p3yb_base = buf + lc * TPAD + 4 * tb;
    const float* p3yc_base = buf + (192 + (lc >> 1) + 32 * (lc & 1)) * TPAD + 4 * tb;
    const float* p3_w  = SW2s + lc * WPAD + 4 * oq;
    const float* p3yb = p3yb_base + BSZ;
    const float* p3yc = p3yc_base + BSZ;
    float* p3out = ob + (size_t)(4 * tb) * 16 + 4 * oq;   // advances TT*16/slot

    // Stager: dst buffer (k+2)%3 (init buffer 1, advance -> 2 at k=0);
    // src global pointer advances TT*16 floats per slot (tile k+2; init tile 2).
    float* stg_dst = xsd + XSZ + sjh * 8 * XPAD + sjt;
    float* stg_dst_base = xsd + sjh * 8 * XPAD + sjt;
    const float4* stg_src = (const float4*)(xb + (2 * TT + sjt) * 16 + sjh * 8);

    __syncthreads();

    // ===== P1 tile (writes via rotating p1r0/p1r1, reads rotating p1xs) =====
#define P1_TILE(R0, R1, XS)                                                   \
    {                                                                         \
        _Pragma("unroll")                                                     \
        for (int g = 0; g < 4; ++g) {                                         \
            const int t = g * 4;                                              \
            u64 a0 = 0, a1 = 0, a2 = 0, a3 = 0;                               \
            _Pragma("unroll")                                                 \
            for (int f = 0; f < 16; ++f) {                                    \
                float4 xq = *(const float4*)((XS) + f * XPAD + t);            \
                a0 = ffma2(wreg[f], dup2(xq.x), a0);                          \
                a1 = ffma2(wreg[f], dup2(xq.y), a1);                          \
                a2 = ffma2(wreg[f], dup2(xq.z), a2);                          \
                a3 = ffma2(wreg[f], dup2(xq.w), a3);                          \
            }                                                                 \
            float2 h0 = unpack2(a0), h1 = unpack2(a1);                        \
            float2 h2 = unpack2(a2), h3 = unpack2(a3);                        \
            float4 v0; v0.x = h0.x; v0.y = h1.x; v0.z = h2.x; v0.w = h3.x;    \
            float4 v1; v1.x = h0.y; v1.y = h1.y; v1.z = h2.y; v1.w = h3.y;    \
            *(float4*)((R0) + t) = v0;                                        \
            *(float4*)((R1) + t) = v1;                                        \
        }                                                                     \
    }

    // ===== P3 tile (reads rotating p3yb/p3yc, writes p3out) =====
#define P3_TILE(YB, YC, OUTP)                                                 \
    {                                                                         \
        u64 acc[8];                                                           \
        _Pragma("unroll")                                                     \
        for (int m = 0; m < 8; ++m) acc[m] = 0ull;                            \
        _Pragma("unroll 4")                                                   \
        for (int i = 0; i < 24; ++i) {                                        \
            ulonglong2 yv = *(const ulonglong2*)((YB) + i * 8 * TPAD);        \
            ulonglong2 wv = *(const ulonglong2*)(p3_w + i * 8 * WPAD);        \
            float2 y01 = unpack2(yv.x), y23 = unpack2(yv.y);                  \
            u64 y0 = dup2(y01.x), y1 = dup2(y01.y);                           \
            u64 y2 = dup2(y23.x), y3 = dup2(y23.y);                           \
            acc[0] = ffma2(wv.x, y0, acc[0]); acc[1] = ffma2(wv.y, y0, acc[1]); \
            acc[2] = ffma2(wv.x, y1, acc[2]); acc[3] = ffma2(wv.y, y1, acc[3]); \
            acc[4] = ffma2(wv.x, y2, acc[4]); acc[5] = ffma2(wv.y, y2, acc[5]); \
            acc[6] = ffma2(wv.x, y3, acc[6]); acc[7] = ffma2(wv.y, y3, acc[7]); \
        }                                                                     \
        _Pragma("unroll 4")                                                   \
        for (int i = 24; i < 32; ++i) {                                       \
            ulonglong2 yv = *(const ulonglong2*)((YC) + (i - 24) * 4 * TPAD); \
            ulonglong2 wv = *(const ulonglong2*)(p3_w + i * 8 * WPAD);        \
            float2 y01 = unpack2(yv.x), y23 = unpack2(yv.y);                  \
            u64 y0 = dup2(y01.x), y1 = dup2(y01.y);                           \
            u64 y2 = dup2(y23.x), y3 = dup2(y23.y);                           \
            acc[0] = ffma2(wv.x, y0, acc[0]); acc[1] = ffma2(wv.y, y0, acc[1]); \
            acc[2] = ffma2(wv.x, y1, acc[2]); acc[3] = ffma2(wv.y, y1, acc[3]); \
            acc[4] = ffma2(wv.x, y2, acc[4]); acc[5] = ffma2(wv.y, y2, acc[5]); \
            acc[6] = ffma2(wv.x, y3, acc[6]); acc[7] = ffma2(wv.y, y3, acc[7]); \
        }                                                                     \
        _Pragma("unroll")                                                     \
        for (int m = 0; m < 8; ++m) {                                         \
            acc[m] = addf2(acc[m], __shfl_xor_sync(0xffffffffu, acc[m], 1));  \
            acc[m] = addf2(acc[m], __shfl_xor_sync(0xffffffffu, acc[m], 2));  \
            acc[m] = addf2(acc[m], __shfl_xor_sync(0xffffffffu, acc[m], 4));  \
        }                                                                     \
        if (lc == 0) {                                                        \
            _Pragma("unroll")                                                 \
            for (int j = 0; j < 4; ++j) {                                     \
                float2 p0 = unpack2(acc[2 * j]);                              \
                float2 p1 = unpack2(acc[2 * j + 1]);                          \
                float4 v; v.x = p0.x; v.y = p0.y; v.z = p1.x; v.w = p1.y;     \
                *(float4*)((OUTP) + j * 16) = v;                              \
            }                                                                 \
        }                                                                     \
    }

    // ---- Fill: P1(0) into buffer 0 ----
    if (isP1) P1_TILE(p1r0_base, p1r1_base, xsd);
    __syncthreads();

    // ---- Pipelined slots (rolled; drain folded in at k = NTILES) ----
    for (int k = 0; k <= NTILES; ++k) {
        if (isP3) {
            p3yb += BSZ; if (p3yb >= p3yb_base + 3 * BSZ) p3yb = p3yb_base;
            p3yc += BSZ; if (p3yc >= p3yc_base + 3 * BSZ) p3yc = p3yc_base;
            if (k >= 1) {
                P3_TILE(p3yb, p3yc, p3out);
                p3out += TT * 16;
            }
        } else if (isP1) {
            p1r0 += BSZ; if (p1r0 >= p1r0_base + 3 * BSZ) p1r0 = p1r0_base;
            p1r1 += BSZ; if (p1r1 >= p1r1_base + 3 * BSZ) p1r1 = p1r1_base;
            p1xs += XSZ; if (p1xs >= xsd + 3 * XSZ) p1xs = xsd;
            if (k + 1 < NTILES) P1_TILE(p1r0, p1r1, p1xs);
        } else if (s < 64) {
            sb_a += BSZ; if (sb_a >= sb_a_base + 3 * BSZ) sb_a = sb_a_base;
            if (k < NTILES) {
                float* r0 = sb_a;
#pragma unroll
                for (int g = 0; g < 4; ++g) {
                    float4 E1 = *(float4*)(r0 + 4 * g);
                    float4 E2 = *(float4*)(r0 + TPAD + 4 * g);
                    float4 E3 = *(float4*)(r0 + 2 * TPAD + 4 * g);
                    j2_step(E1.x, E2.x, E3.x, ep1, ep2, ep12, epbar);
                    j2_step(E1.y, E2.y, E3.y, ep1, ep2, ep12, epbar);
                    j2_step(E1.z, E2.z, E3.z, ep1, ep2, ep12, epbar);
                    j2_step(E1.w, E2.w, E3.w, ep1, ep2, ep12, epbar);
                    *(float4*)(r0 + 4 * g) = E1;
                    *(float4*)(r0 + TPAD + 4 * g) = E2;
                    *(float4*)(r0 + 2 * TPAD + 4 * g) = E3;
                }
            }
        } else if (s < 96) {
            sb_a += BSZ; if (sb_a >= sb_a_base + 3 * BSZ) sb_a = sb_a_base;
            sb_b += BSZ; if (sb_b >= sb_b_base + 3 * BSZ) sb_b = sb_b_base;
            if (k < NTILES) {
#pragma unroll
                for (int g = 0; g < 4; ++g) {
                    float4 DN = *(float4*)(sb_a + 4 * g);
                    float4 DS = *(float4*)(sb_b + 4 * g);
                    coh_step(DN.x, DS.x, hist);
                    coh_step(DN.y, DS.y, hist);
                    coh_step(DN.z, DS.z, hist);
                    coh_step(DN.w, DS.w, hist);
                    *(float4*)(sb_a + 4 * g) = DN;
                    *(float4*)(sb_b + 4 * g) = DS;
                }
            }
        } else {
            stg_dst += XSZ; if (stg_dst >= stg_dst_base + 3 * XSZ) stg_dst = stg_dst_base;
            if (k + 2 < NTILES) {
                float4 v0 = stg_src[0], v1 = stg_src[1];
                stg_dst[0*XPAD] = v0.x; stg_dst[1*XPAD] = v0.y;
                stg_dst[2*XPAD] = v0.z; stg_dst[3*XPAD] = v0.w;
                stg_dst[4*XPAD] = v1.x; stg_dst[5*XPAD] = v1.y;
                stg_dst[6*XPAD] = v1.z; stg_dst[7*XPAD] = v1.w;
            }
            stg_src += (TT * 16) / 4;    // advance one tile (float4 units)
        }
        __syncthreads();
    }
}

extern "C" void kernel_launch(void* const* d_in, const int* in_sizes, int n_in,
                              void* d_out, int out_size)
{
    const float* x  = (const float*)d_in[0];
    const float* W1 = (const float*)d_in[1];
    const float* W2 = (const float*)d_in[2];
    float* out = (float*)d_out;

    const size_t smem = (size_t)(256 * WPAD + 3 * XSZ + 3 * BSZ) * sizeof(float); // 85760 B
    cudaFuncSetAttribute(fused_fea_kernel, cudaFuncAttributeMaxDynamicSharedMemorySize, (int)smem);
    fused_fea_kernel<<<256, NTHREADS, smem>>>(x, W1, W2, out);
}

// round 17
// speedup vs baseline: 1.1636x; 1.1329x over previous
#include <cuda_runtime.h>

// Warp-specialized pipeline, 384 threads/CTA, 2 CTAs/SM, one CTA per batch.
//   tid 0-255  (G, 8 warps): P1 (fc1, channel pairs) + P3 (fc2).
//   tid 256-351(S, 3 warps): 96 sequential material chains, 4-t batched LDS/STS.
//   tid 352-383:             stages x tiles global->shared (transposed [f][t]).
// buf layout [l][TPAD] (time contiguous). Slot k: G does P3(k-1), G-barrier,
// P1(k+1); S does P2(k) + stage(k+2) concurrently; one __syncthreads per slot.
// R10 champion with widened P3 unroll (4 -> 8) for deeper LDS batching.

typedef unsigned long long u64;

#define NTHREADS 384
#define TT 32
#define NTILES 32
#define TPAD 36
#define XPAD 36
#define WPAD 20
#define XSZ  (16 * XPAD)
#define BSZ  (256 * TPAD)

__device__ __forceinline__ u64 ffma2(u64 a, u64 b, u64 c) {
    u64 d; asm("fma.rn.f32x2 %0, %1, %2, %3;" : "=l"(d) : "l"(a), "l"(b), "l"(c)); return d;
}
__device__ __forceinline__ u64 addf2(u64 a, u64 b) {
    u64 d; asm("add.rn.f32x2 %0, %1, %2;" : "=l"(d) : "l"(a), "l"(b)); return d;
}
__device__ __forceinline__ u64 pack2(float a, float b) {
    u64 r; asm("mov.b64 %0, {%1, %2};" : "=l"(r) : "f"(a), "f"(b)); return r;
}
__device__ __forceinline__ u64 dup2(float a) {
    u64 r; asm("mov.b64 %0, {%1, %1};" : "=l"(r) : "f"(a)); return r;
}
__device__ __forceinline__ float2 unpack2(u64 v) {
    float2 r; asm("mov.b64 {%0, %1}, %2;" : "=f"(r.x), "=f"(r.y) : "l"(v)); return r;
}

// ---- material constants (reference float32 values) ----
#define NUv    0.3f
#define CEL00  (200.0f / 0.91f)
#define CEL01  (CEL00 * 0.3f)
#define CEL22  (CEL00 * 0.35f)
#define INV_E  (1.0f / 200.0f)
#define INV_G  (2.6f / 200.0f)
#define GMODc  (200.0f / 2.6f)
#define SY0c   2.0f
#define HARDc  10.0f
#define INV3GH (1.0f / (3.0f * GMODc + HARDc))
#define KPEN   50.0f
#define D0c    0.1f
#define INV_DFm (1.0f / 0.9f)

__device__ __forceinline__ void j2_step(float& e1, float& e2, float& e12,
                                        float& ep1, float& ep2, float& ep12, float& epbar)
{
    float d1 = e1 - ep1, d2 = e2 - ep2, d12 = e12 - ep12;
    float s1  = CEL00 * d1 + CEL01 * d2;
    float s2  = CEL01 * d1 + CEL00 * d2;
    float s12 = CEL22 * d12;
    float qv  = fmaxf(s1 * s1 - s1 * s2 + s2 * s2 + 3.0f * s12 * s12, 1e-12f);
    float rs  = rsqrtf(qv);
    float seq = qv * rs;
    float fy  = seq - (SY0c + HARDc * epbar);
    bool  pl  = fy > 0.0f;
    epbar += fmaxf(fy, 0.0f) * INV3GH;
    float r = pl ? (SY0c + HARDc * epbar) * rs : 1.0f;
    s1 *= r; s2 *= r; s12 *= r;
    ep1  = pl ? e1  - (s1 - NUv * s2) * INV_E : ep1;
    ep2  = pl ? e2  - (s2 - NUv * s1) * INV_E : ep2;
    ep12 = pl ? e12 - s12 * INV_G             : ep12;
    e1 = s1; e2 = s2; e12 = s12;
}

__device__ __forceinline__ void coh_step(float& dn, float& ds, float& hist)
{
    float dnp = fmaxf(dn, 0.0f);
    float q2  = fmaxf(dnp * dnp + ds * ds, 1e-12f);
    float lam = q2 * rsqrtf(q2);
    hist = fmaxf(hist, lam);
    float dmg = __fdividef(hist - D0c, hist) * INV_DFm;
    dmg = fminf(fmaxf(dmg, 0.0f), 1.0f);
    float omd = 1.0f - dmg;
    float tn = KPEN * dn * (dn > 0.0f ? omd : 1.0f);
    ds = omd * KPEN * ds;
    dn = tn;
}

// channel -> buf row (cohesive channels stored comp-planar)
__device__ __forceinline__ int row_of(int c) {
    return (c < 192) ? c : 192 + ((c - 192) >> 1) + 32 * (c & 1);
}

__global__ void __launch_bounds__(NTHREADS, 2)
fused_fea_kernel(const float* __restrict__ x, const float* __restrict__ W1,
                 const float* __restrict__ W2, float* __restrict__ out)
{
    extern __shared__ float sm[];
    float* SW2s = sm;                    // 256*WPAD, softplus(W2) [l][o]
    float* xsd  = sm + 256 * WPAD;       // 2 * XSZ, x transposed [f][t]
    float* buf  = xsd + 2 * XSZ;         // 2 * BSZ, [l][t]

    const int tid = threadIdx.x;
    const int b   = blockIdx.x;
    const bool isG = (tid < 256);

    const float* xb = x   + (size_t)b * (1024 * 16);
    float*       ob = out + (size_t)b * (1024 * 16);

    // ---- Prologue ----
    for (int i = tid; i < 4096; i += NTHREADS) {
        int o = i >> 8, l = i & 255;
        SW2s[l * WPAD + o] = log1pf(expf(W2[i]));
    }
    if (tid >= 352) {
        const int j = tid - 352;
#pragma unroll
        for (int tile = 0; tile < 2; ++tile) {
            const float4* src = (const float4*)(xb + tile * (TT * 16) + j * 16);
            float* dst = xsd + tile * XSZ + j;
            float4 v0 = src[0], v1 = src[1], v2 = src[2], v3 = src[3];
            dst[0*XPAD] = v0.x; dst[1*XPAD]  = v0.y; dst[2*XPAD]  = v0.z; dst[3*XPAD]  = v0.w;
            dst[4*XPAD] = v1.x; dst[5*XPAD]  = v1.y; dst[6*XPAD]  = v1.z; dst[7*XPAD]  = v1.w;
            dst[8*XPAD] = v2.x; dst[9*XPAD]  = v2.y; dst[10*XPAD] = v2.z; dst[11*XPAD] = v2.w;
            dst[12*XPAD]= v3.x; dst[13*XPAD] = v3.y; dst[14*XPAD] = v3.z; dst[15*XPAD] = v3.w;
        }
    }

    // G/P1 setup: packed channel pair (c, c+128), c = tid&127; warp t-half th.
    u64 wreg[16];
    int row0 = 0, row1 = 0, th = 0;
    if (isG) {
        const int c = tid & 127;
        th = tid >> 7;                   // 0: t 0..15, 1: t 16..31
        row0 = row_of(c);
        row1 = row_of(c + 128);
#pragma unroll
        for (int f = 0; f < 16; ++f)
            wreg[f] = pack2(W1[c * 16 + f], W1[(c + 128) * 16 + f]);
    }

    // S chain state
    float ep1 = 0.f, ep2 = 0.f, ep12 = 0.f, epbar = 0.f, hist = 0.f;
    const int s = tid - 256;

    // P3 coords: lc = l-strip (l = 8i+lc), oq = output quad, tb = 4-t group.
    const int lc = tid & 7;
    const int oq = (tid >> 3) & 3;
    const int tb = tid >> 5;
    const int rowc_base = 192 + (lc >> 1) + 32 * (lc & 1);

    __syncthreads();

    // ===== P1: channel pair o-packed, warp covers 16 t (4 groups of 4) =====
#define P1_TILE(BSEL, XSEL)                                                   \
    {                                                                         \
        float* bufb = buf + (BSEL) * BSZ;                                     \
        const float* xsb = xsd + (XSEL) * XSZ + 16 * th;                      \
        _Pragma("unroll")                                                     \
        for (int g = 0; g < 4; ++g) {                                         \
            const int t = g * 4;                                              \
            u64 a0 = 0, a1 = 0, a2 = 0, a3 = 0;                               \
            _Pragma("unroll")                                                 \
            for (int f = 0; f < 16; ++f) {                                    \
                float4 xq = *(const float4*)(xsb + f * XPAD + t);             \
                a0 = ffma2(wreg[f], dup2(xq.x), a0);                          \
                a1 = ffma2(wreg[f], dup2(xq.y), a1);                          \
                a2 = ffma2(wreg[f], dup2(xq.z), a2);                          \
                a3 = ffma2(wreg[f], dup2(xq.w), a3);                          \
            }                                                                 \
            float2 h0 = unpack2(a0), h1 = unpack2(a1);                        \
            float2 h2 = unpack2(a2), h3 = unpack2(a3);                        \
            float4 v0; v0.x = h0.x; v0.y = h1.x; v0.z = h2.x; v0.w = h3.x;    \
            float4 v1; v1.x = h0.y; v1.y = h1.y; v1.z = h2.y; v1.w = h3.y;    \
            *(float4*)(bufb + row0 * TPAD + 16 * th + t) = v0;                \
            *(float4*)(bufb + row1 * TPAD + 16 * th + t) = v1;                \
        }                                                                     \
    }

    // ===== P3 (champion shape; unroll widened 4 -> 8) =====
#define P3_TILE(BSEL, TOUT)                                                   \
    {                                                                         \
        const float* bufb = buf + (BSEL) * BSZ;                               \
        u64 acc[8];                                                           \
        _Pragma("unroll")                                                     \
        for (int m = 0; m < 8; ++m) acc[m] = 0ull;                            \
        const float* ybulk = bufb + lc * TPAD + 4 * tb;                       \
        const float* wrow  = SW2s + lc * WPAD + 4 * oq;                       \
        _Pragma("unroll 8")                                                   \
        for (int i = 0; i < 24; ++i) {                                        \
            ulonglong2 yv = *(const ulonglong2*)(ybulk + i * 8 * TPAD);       \
            ulonglong2 wv = *(const ulonglong2*)(wrow + i * 8 * WPAD);        \
            float2 y01 = unpack2(yv.x), y23 = unpack2(yv.y);                  \
            u64 y0 = dup2(y01.x), y1 = dup2(y01.y);                           \
            u64 y2 = dup2(y23.x), y3 = dup2(y23.y);                           \
            acc[0] = ffma2(wv.x, y0, acc[0]); acc[1] = ffma2(wv.y, y0, acc[1]); \
            acc[2] = ffma2(wv.x, y1, acc[2]); acc[3] = ffma2(wv.y, y1, acc[3]); \
            acc[4] = ffma2(wv.x, y2, acc[4]); acc[5] = ffma2(wv.y, y2, acc[5]); \
            acc[6] = ffma2(wv.x, y3, acc[6]); acc[7] = ffma2(wv.y, y3, acc[7]); \
        }                                                                     \
        const float* ycoh = bufb + rowc_base * TPAD + 4 * tb;                 \
        _Pragma("unroll")                                                     \
        for (int i = 24; i < 32; ++i) {                                       \
            ulonglong2 yv = *(const ulonglong2*)(ycoh + (i - 24) * 4 * TPAD); \
            ulonglong2 wv = *(const ulonglong2*)(wrow + i * 8 * WPAD);        \
            float2 y01 = unpack2(yv.x), y23 = unpack2(yv.y);                  \
            u64 y0 = dup2(y01.x), y1 = dup2(y01.y);                           \
            u64 y2 = dup2(y23.x), y3 = dup2(y23.y);                           \
            acc[0] = ffma2(wv.x, y0, acc[0]); acc[1] = ffma2(wv.y, y0, acc[1]); \
            acc[2] = ffma2(wv.x, y1, acc[2]); acc[3] = ffma2(wv.y, y1, acc[3]); \
            acc[4] = ffma2(wv.x, y2, acc[4]); acc[5] = ffma2(wv.y, y2, acc[5]); \
            acc[6] = ffma2(wv.x, y3, acc[6]); acc[7] = ffma2(wv.y, y3, acc[7]); \
        }                                                                     \
        _Pragma("unroll")                                                     \
        for (int m = 0; m < 8; ++m) {                                         \
            acc[m] = addf2(acc[m], __shfl_xor_sync(0xffffffffu, acc[m], 1));  \
            acc[m] = addf2(acc[m], __shfl_xor_sync(0xffffffffu, acc[m], 2));  \
            acc[m] = addf2(acc[m], __shfl_xor_sync(0xffffffffu, acc[m], 4));  \
        }                                                                     \
        if (lc == 0) {                                                        \
            float* ogp = ob + (size_t)((TOUT) + 4 * tb) * 16 + 4 * oq;        \
            _Pragma("unroll")                                                 \
            for (int j = 0; j < 4; ++j) {                                     \
                float2 p0 = unpack2(acc[2 * j]);                              \
                float2 p1 = unpack2(acc[2 * j + 1]);                          \
                float4 v; v.x = p0.x; v.y = p0.y; v.z = p1.x; v.w = p1.y;     \
                *(float4*)(ogp + j * 16) = v;                                 \
            }                                                                 \
        }                                                                     \
    }

    // ---- Fill: P1(0) ----
    if (isG) P1_TILE(0, 0);
    __syncthreads();

    // ---- Pipelined slots ----
    for (int k = 0; k < NTILES; ++k) {
        if (isG) {
            if (k >= 1) P3_TILE((k - 1) & 1, (k - 1) * TT);
            // G-only barrier: P3 reads complete before P1(k+1) overwrites buffer.
            asm volatile("bar.sync 1, 256;" ::: "memory");
            if (k + 1 < NTILES) P1_TILE((k + 1) & 1, (k + 1) & 1);
        } else if (s < 64) {
            // J2 bulk: rows 3s..3s+2; 4 timesteps per LDS/STS.128.
            float* r0 = buf + (k & 1) * BSZ + (3 * s) * TPAD;
#pragma unroll
            for (int g = 0; g < 8; ++g) {
                float4 E1 = *(float4*)(r0 + 4 * g);
                float4 E2 = *(float4*)(r0 + TPAD + 4 * g);
                float4 E3 = *(float4*)(r0 + 2 * TPAD + 4 * g);
                j2_step(E1.x, E2.x, E3.x, ep1, ep2, ep12, epbar);
                j2_step(E1.y, E2.y, E3.y, ep1, ep2, ep12, epbar);
                j2_step(E1.z, E2.z, E3.z, ep1, ep2, ep12, epbar);
                j2_step(E1.w, E2.w, E3.w, ep1, ep2, ep12, epbar);
                *(float4*)(r0 + 4 * g) = E1;
                *(float4*)(r0 + TPAD + 4 * g) = E2;
                *(float4*)(r0 + 2 * TPAD + 4 * g) = E3;
            }
        } else if (s < 96) {
            // Cohesive: dn row 192+j, ds row 224+j.
            const int j = s - 64;
            float* rdn = buf + (k & 1) * BSZ + (192 + j) * TPAD;
            float* rds = buf + (k & 1) * BSZ + (224 + j) * TPAD;
#pragma unroll
            for (int g = 0; g < 8; ++g) {
                float4 DN = *(float4*)(rdn + 4 * g);
                float4 DS = *(float4*)(rds + 4 * g);
                coh_step(DN.x, DS.x, hist);
                coh_step(DN.y, DS.y, hist);
                coh_step(DN.z, DS.z, hist);
                coh_step(DN.w, DS.w, hist);
                *(float4*)(rdn + 4 * g) = DN;
                *(float4*)(rds + 4 * g) = DS;
            }
        } else {
            // Stager: x tile (k+2) -> xsd[k&1], transposed [f][t].
            if (k + 2 < NTILES) {
                const int j = tid - 352;
                const float4* src = (const float4*)(xb + (k + 2) * (TT * 16) + j * 16);
                float* dst = xsd + (k & 1) * XSZ + j;
                float4 v0 = src[0], v1 = src[1], v2 = src[2], v3 = src[3];
                dst[0*XPAD] = v0.x; dst[1*XPAD]  = v0.y; dst[2*XPAD]  = v0.z; dst[3*XPAD]  = v0.w;
                dst[4*XPAD] = v1.x; dst[5*XPAD]  = v1.y; dst[6*XPAD]  = v1.z; dst[7*XPAD]  = v1.w;
                dst[8*XPAD] = v2.x; dst[9*XPAD]  = v2.y; dst[10*XPAD] = v2.z; dst[11*XPAD] = v2.w;
                dst[12*XPAD]= v3.x; dst[13*XPAD] = v3.y; dst[14*XPAD] = v3.z; dst[15*XPAD] = v3.w;
            }
        }
        __syncthreads();
    }

    // ---- Drain: P3(NTILES-1) ----
    if (isG) P3_TILE((NTILES - 1) & 1, (NTILES - 1) * TT);
}

extern "C" void kernel_launch(void* const* d_in, const int* in_sizes, int n_in,
                              void* d_out, int out_size)
{
    const float* x  = (const float*)d_in[0];
    const float* W1 = (const float*)d_in[1];
    const float* W2 = (const float*)d_in[2];
    float* out = (float*)d_out;

    const size_t smem = (size_t)(256 * WPAD + 2 * XSZ + 2 * BSZ) * sizeof(float); // 98816 B
    cudaFuncSetAttribute(fused_fea_kernel, cudaFuncAttributeMaxDynamicSharedMemorySize, (int)smem);
    fused_fea_kernel<<<256, NTHREADS, smem>>>(x, W1, W2, out);
}